// round 14
// baseline (speedup 1.0000x reference)
#include <cuda_runtime.h>

#define Hdim 1024
#define Wdim 1024
#define HWdim (Hdim * Wdim)
#define TSH 32
#define TSW 32
#define NT 128

// smem float offsets (all even -> 8B alignment for float2 LDS)
#define OFF_X   0            // [3][38][38]
#define OFF_C4  4332         // [36][36]
#define OFF_C5  5628         // [34][34]
#define OFF_W   6784         // [108]
#define OFF_B   6892         // [3]
#define OFF_M   6896         // [12]
#define OFF_B2  6908         // [2]
#define SMEM_FLOATS 6910
#define SMEM_BYTES (SMEM_FLOATS * 4)

__device__ float g_M[12];
__device__ float g_B[2];

__global__ void fold_mlp_kernel(const float* __restrict__ lw1,
                                const float* __restrict__ lb1,
                                const float* __restrict__ lw2,
                                const float* __restrict__ lb2) {
    int t = threadIdx.x;
    if (t < 12) {
        int o = t / 6, c = t % 6;
        float acc = 0.0f;
        #pragma unroll 8
        for (int k = 0; k < 128; k++)
            acc += lw2[o * 128 + k] * lw1[k * 6 + c];
        g_M[t] = acc;
    } else if (t < 14) {
        int o = t - 12;
        float acc = lb2[o];
        #pragma unroll 8
        for (int k = 0; k < 128; k++)
            acc += lw2[o * 128 + k] * lb1[k];
        g_B[o] = acc;
    }
}

__device__ __forceinline__ float sigmoidf_(float y) {
    return 1.0f / (1.0f + __expf(-y));
}

// 2x4-output conv accumulate; window = 4 rows x 6 cols starting at P
// (P 8B-aligned). Accumulates into a00..a03 (row j), a10..a13 (row j+1).
#define ACC2X4_EVEN(P, S, WSM) do {                                           \
    float wc[9];                                                              \
    _Pragma("unroll")                                                         \
    for (int kk = 0; kk < 9; kk++) wc[kk] = (WSM)[kk];                        \
    _Pragma("unroll")                                                         \
    for (int rr = 0; rr < 4; rr++) {                                          \
        float2 A = *(const float2*)((P) + rr * (S));                          \
        float2 B = *(const float2*)((P) + rr * (S) + 2);                      \
        float2 C = *(const float2*)((P) + rr * (S) + 4);                      \
        if (rr <= 2) {                                                        \
            a00 += wc[rr*3+0]*A.x + wc[rr*3+1]*A.y + wc[rr*3+2]*B.x;          \
            a01 += wc[rr*3+0]*A.y + wc[rr*3+1]*B.x + wc[rr*3+2]*B.y;          \
            a02 += wc[rr*3+0]*B.x + wc[rr*3+1]*B.y + wc[rr*3+2]*C.x;          \
            a03 += wc[rr*3+0]*B.y + wc[rr*3+1]*C.x + wc[rr*3+2]*C.y;          \
        }                                                                     \
        if (rr >= 1) {                                                        \
            a10 += wc[(rr-1)*3+0]*A.x + wc[(rr-1)*3+1]*A.y + wc[(rr-1)*3+2]*B.x; \
            a11 += wc[(rr-1)*3+0]*A.y + wc[(rr-1)*3+1]*B.x + wc[(rr-1)*3+2]*B.y; \
            a12 += wc[(rr-1)*3+0]*B.x + wc[(rr-1)*3+1]*B.y + wc[(rr-1)*3+2]*C.x; \
            a13 += wc[(rr-1)*3+0]*B.y + wc[(rr-1)*3+1]*C.x + wc[(rr-1)*3+2]*C.y; \
        }                                                                     \
    }                                                                         \
} while (0)

// Window logically starts at P+1 (cols 1..6 of P): extra scalar for col 6.
#define ACC2X4_ODD(P, S, WSM) do {                                            \
    float wc[9];                                                              \
    _Pragma("unroll")                                                         \
    for (int kk = 0; kk < 9; kk++) wc[kk] = (WSM)[kk];                        \
    _Pragma("unroll")                                                         \
    for (int rr = 0; rr < 4; rr++) {                                          \
        float2 A = *(const float2*)((P) + rr * (S));                          \
        float2 B = *(const float2*)((P) + rr * (S) + 2);                      \
        float2 C = *(const float2*)((P) + rr * (S) + 4);                      \
        float  Dx = (P)[rr * (S) + 6];                                        \
        if (rr <= 2) {                                                        \
            a00 += wc[rr*3+0]*A.y + wc[rr*3+1]*B.x + wc[rr*3+2]*B.y;          \
            a01 += wc[rr*3+0]*B.x + wc[rr*3+1]*B.y + wc[rr*3+2]*C.x;          \
            a02 += wc[rr*3+0]*B.y + wc[rr*3+1]*C.x + wc[rr*3+2]*C.y;          \
            a03 += wc[rr*3+0]*C.x + wc[rr*3+1]*C.y + wc[rr*3+2]*Dx;           \
        }                                                                     \
        if (rr >= 1) {                                                        \
            a10 += wc[(rr-1)*3+0]*A.y + wc[(rr-1)*3+1]*B.x + wc[(rr-1)*3+2]*B.y; \
            a11 += wc[(rr-1)*3+0]*B.x + wc[(rr-1)*3+1]*B.y + wc[(rr-1)*3+2]*C.x; \
            a12 += wc[(rr-1)*3+0]*B.y + wc[(rr-1)*3+1]*C.x + wc[(rr-1)*3+2]*C.y; \
            a13 += wc[(rr-1)*3+0]*C.x + wc[(rr-1)*3+1]*C.y + wc[(rr-1)*3+2]*Dx; \
        }                                                                     \
    }                                                                         \
} while (0)

__global__ __launch_bounds__(NT, 8) void unet_fused_kernel(
    const float* __restrict__ x,  const float* __restrict__ x2,
    const float* __restrict__ w1a, const float* __restrict__ b1a,
    const float* __restrict__ w2a, const float* __restrict__ b2a,
    const float* __restrict__ w3a, const float* __restrict__ b3a,
    const float* __restrict__ w1b, const float* __restrict__ b1b,
    const float* __restrict__ w2b, const float* __restrict__ b2b,
    const float* __restrict__ w3b, const float* __restrict__ b3b,
    float* __restrict__ outf, float* __restrict__ den1, float* __restrict__ den2)
{
    extern __shared__ float sm[];
    float* s_x  = sm + OFF_X;    // [3][38][38]
    float* s_c4 = sm + OFF_C4;   // [36][36]
    float* s_c5 = sm + OFF_C5;   // [34][34]
    float* s_w  = sm + OFF_W;
    float* s_b  = sm + OFF_B;
    float* s_M  = sm + OFF_M;
    float* s_B2 = sm + OFF_B2;

    const int tid = threadIdx.x;
    const int h0  = blockIdx.y * TSH;
    const int w0  = blockIdx.x * TSW;

    if (tid < 12) s_M[tid] = g_M[tid];
    if (tid >= 12 && tid < 14) s_B2[tid - 12] = g_B[tid - 12];

    #pragma unroll 1
    for (int e = 0; e < 2; e++) {
        const float* X   = e ? x2  : x;
        const float* W1  = e ? w1b : w1a;
        const float* W2  = e ? w2b : w2a;
        const float* W3  = e ? w3b : w3a;
        const float* B1  = e ? b1b : b1a;
        const float* Bc2 = e ? b2b : b2a;
        const float* B3  = e ? b3b : b3a;
        float* den = e ? den2 : den1;

        __syncthreads();  // protect smem reuse across encoders

        // ---- weights + biases ----
        if (tid < 108) {
            float v;
            if (tid < 27)      v = __ldg(&W1[tid]);
            else if (tid < 63) v = __ldg(&W2[tid - 27]);
            else               v = __ldg(&W3[tid - 63]);
            s_w[tid] = v;
        }
        if (tid == 120) s_b[0] = __ldg(&B1[0]);
        if (tid == 121) s_b[1] = __ldg(&Bc2[0]);
        if (tid == 122) s_b[2] = __ldg(&B3[0]);

        // ---- input tile (3 ch, 38x38, 3-halo, zero padded) ----
        #pragma unroll 1
        for (int c = 0; c < 3; c++) {
            #pragma unroll 1
            for (int idx = tid; idx < 38 * 38; idx += NT) {
                int r = idx / 38;
                int q = idx - r * 38;
                int gh = h0 - 3 + r, gw = w0 - 3 + q;
                float v = 0.0f;
                if ((unsigned)gh < (unsigned)Hdim && (unsigned)gw < (unsigned)Wdim)
                    v = __ldg(&X[c * HWdim + gh * Wdim + gw]);
                s_x[c * 1444 + idx] = v;
            }
        }
        __syncthreads();

        // ===== conv1: 3ch -> c4 (36x36), 2x4 blocked =====
        // Outside-image positions must be 0 (reference zero-pads the
        // concatenated tensor).
        {
            #pragma unroll 1
            for (int item = tid; item < 18 * 9; item += NT) {
                int rp = item / 9;
                int cg = item - rp * 9;
                int j = rp * 2, i = cg * 4;
                float a00 = 0, a01 = 0, a02 = 0, a03 = 0;
                float a10 = 0, a11 = 0, a12 = 0, a13 = 0;
                ACC2X4_EVEN(s_x + 0 * 1444 + j * 38 + i, 38, s_w + 0);
                ACC2X4_EVEN(s_x + 1 * 1444 + j * 38 + i, 38, s_w + 9);
                ACC2X4_EVEN(s_x + 2 * 1444 + j * 38 + i, 38, s_w + 18);
                float bia = s_b[0];
                int gw = w0 + i - 2, gh = h0 + j - 2;
                bool hc0 = (unsigned)gh < (unsigned)Hdim;
                bool hc1 = (unsigned)(gh + 1) < (unsigned)Hdim;
                float4 r0, r1;
                {
                    bool wq0 = (unsigned)(gw + 0) < (unsigned)Wdim;
                    bool wq1 = (unsigned)(gw + 1) < (unsigned)Wdim;
                    bool wq2 = (unsigned)(gw + 2) < (unsigned)Wdim;
                    bool wq3 = (unsigned)(gw + 3) < (unsigned)Wdim;
                    r0.x = (hc0 && wq0) ? sigmoidf_(bia + a00) : 0.0f;
                    r0.y = (hc0 && wq1) ? sigmoidf_(bia + a01) : 0.0f;
                    r0.z = (hc0 && wq2) ? sigmoidf_(bia + a02) : 0.0f;
                    r0.w = (hc0 && wq3) ? sigmoidf_(bia + a03) : 0.0f;
                    r1.x = (hc1 && wq0) ? sigmoidf_(bia + a10) : 0.0f;
                    r1.y = (hc1 && wq1) ? sigmoidf_(bia + a11) : 0.0f;
                    r1.z = (hc1 && wq2) ? sigmoidf_(bia + a12) : 0.0f;
                    r1.w = (hc1 && wq3) ? sigmoidf_(bia + a13) : 0.0f;
                }
                *(float4*)(s_c4 + j * 36 + i)       = r0;   // (36j+i)%4==0
                *(float4*)(s_c4 + (j + 1) * 36 + i) = r1;
            }
        }
        __syncthreads();

        // ===== conv2: [x,c4] -> c5 (34x34), 2x4 blocked =====
        {
            #pragma unroll 1
            for (int item = tid; item < 17 * 9; item += NT) {
                int rp = item / 9;
                int cg = item - rp * 9;
                int j = rp * 2;
                int i = cg * 4; if (i > 30) i = 30;   // cols 30..33 dup (benign)
                float a00 = 0, a01 = 0, a02 = 0, a03 = 0;
                float a10 = 0, a11 = 0, a12 = 0, a13 = 0;
                // x window cols i+1..i+6, rows j+1..j+4
                ACC2X4_ODD (s_x + 0 * 1444 + (j + 1) * 38 + i, 38, s_w + 27);
                ACC2X4_ODD (s_x + 1 * 1444 + (j + 1) * 38 + i, 38, s_w + 36);
                ACC2X4_ODD (s_x + 2 * 1444 + (j + 1) * 38 + i, 38, s_w + 45);
                ACC2X4_EVEN(s_c4 + j * 36 + i,                  36, s_w + 54);
                float bia = s_b[1];
                int gw = w0 + i - 1, gh = h0 + j - 1;
                bool hc0 = (unsigned)gh < (unsigned)Hdim;
                bool hc1 = (unsigned)(gh + 1) < (unsigned)Hdim;
                bool wq0 = (unsigned)(gw + 0) < (unsigned)Wdim;
                bool wq1 = (unsigned)(gw + 1) < (unsigned)Wdim;
                bool wq2 = (unsigned)(gw + 2) < (unsigned)Wdim;
                bool wq3 = (unsigned)(gw + 3) < (unsigned)Wdim;
                float2 p0a = make_float2(hc0 && wq0 ? sigmoidf_(bia + a00) : 0.0f,
                                         hc0 && wq1 ? sigmoidf_(bia + a01) : 0.0f);
                float2 p0b = make_float2(hc0 && wq2 ? sigmoidf_(bia + a02) : 0.0f,
                                         hc0 && wq3 ? sigmoidf_(bia + a03) : 0.0f);
                float2 p1a = make_float2(hc1 && wq0 ? sigmoidf_(bia + a10) : 0.0f,
                                         hc1 && wq1 ? sigmoidf_(bia + a11) : 0.0f);
                float2 p1b = make_float2(hc1 && wq2 ? sigmoidf_(bia + a12) : 0.0f,
                                         hc1 && wq3 ? sigmoidf_(bia + a13) : 0.0f);
                // 8B-aligned stores (i may be 30 -> not 16B aligned)
                *(float2*)(s_c5 + j * 34 + i)           = p0a;
                *(float2*)(s_c5 + j * 34 + i + 2)       = p0b;
                *(float2*)(s_c5 + (j + 1) * 34 + i)     = p1a;
                *(float2*)(s_c5 + (j + 1) * 34 + i + 2) = p1b;
            }
        }
        __syncthreads();

        // ===== conv3: [x,c4,c5] -> c6 + den + outf (32x32), 1 item/thread =====
        {
            const int rp = tid >> 3;    // 16 row pairs
            const int cg = tid & 7;     // 8 col groups
            const int j = rp * 2, i = cg * 4;
            float a00 = 0, a01 = 0, a02 = 0, a03 = 0;
            float a10 = 0, a11 = 0, a12 = 0, a13 = 0;
            ACC2X4_EVEN(s_x + 0 * 1444 + (j + 2) * 38 + (i + 2), 38, s_w + 63);
            ACC2X4_EVEN(s_x + 1 * 1444 + (j + 2) * 38 + (i + 2), 38, s_w + 72);
            ACC2X4_EVEN(s_x + 2 * 1444 + (j + 2) * 38 + (i + 2), 38, s_w + 81);
            ACC2X4_ODD (s_c4 + (j + 1) * 36 + i,                  36, s_w + 90);
            ACC2X4_EVEN(s_c5 + j * 34 + i,                        34, s_w + 99);
            const float bia = s_b[2];

            float accs[2][4] = {{a00, a01, a02, a03}, {a10, a11, a12, a13}};
            #pragma unroll
            for (int r = 0; r < 2; r++) {
                int jj = j + r;
                #pragma unroll
                for (int cp = 0; cp < 4; cp += 2) {
                    int ii = i + cp;
                    float fA5 = sigmoidf_(bia + accs[r][cp + 0]);
                    float fB5 = sigmoidf_(bia + accs[r][cp + 1]);
                    const float* xc = s_x + (jj + 3) * 38 + (ii + 3);
                    float fA0 = xc[0],    fB0 = xc[1];
                    float fA1 = xc[1444], fB1 = xc[1445];
                    float fA2 = xc[2888], fB2 = xc[2889];
                    float fA3 = s_c4[(jj + 2) * 36 + (ii + 2)];
                    float fB3 = s_c4[(jj + 2) * 36 + (ii + 3)];
                    float fA4 = s_c5[(jj + 1) * 34 + (ii + 1)];
                    float fB4 = s_c5[(jj + 1) * 34 + (ii + 2)];

                    int pix = (h0 + jj) * Wdim + (w0 + ii);   // even
                    float4* dp = (float4*)(den + (size_t)pix * 6);
                    dp[0] = make_float4(fA0, fA1, fA2, fA3);
                    dp[1] = make_float4(fA4, fA5, fB0, fB1);
                    dp[2] = make_float4(fB2, fB3, fB4, fB5);

                    float mA0 = s_M[0]*fA0 + s_M[1]*fA1 + s_M[2]*fA2
                              + s_M[3]*fA3 + s_M[4]*fA4 + s_M[5]*fA5;
                    float mA1 = s_M[6]*fA0 + s_M[7]*fA1 + s_M[8]*fA2
                              + s_M[9]*fA3 + s_M[10]*fA4 + s_M[11]*fA5;
                    float mB0 = s_M[0]*fB0 + s_M[1]*fB1 + s_M[2]*fB2
                              + s_M[3]*fB3 + s_M[4]*fB4 + s_M[5]*fB5;
                    float mB1 = s_M[6]*fB0 + s_M[7]*fB1 + s_M[8]*fB2
                              + s_M[9]*fB3 + s_M[10]*fB4 + s_M[11]*fB5;

                    float4* op = (float4*)(outf + (size_t)pix * 2);
                    if (e == 0) {
                        *op = make_float4(s_B2[0] + mA0, s_B2[1] + mA1,
                                          s_B2[0] + mB0, s_B2[1] + mB1);
                    } else {
                        float4 prev = *op;  // same thread wrote it in e=0
                        *op = make_float4(prev.x - mA0, prev.y - mA1,
                                          prev.z - mB0, prev.w - mB1);
                    }
                }
            }
        }
    }
}

extern "C" void kernel_launch(void* const* d_in, const int* in_sizes, int n_in,
                              void* d_out, int out_size) {
    const float* x   = (const float*)d_in[0];
    const float* x2  = (const float*)d_in[1];
    const float* w1a = (const float*)d_in[2];
    const float* b1a = (const float*)d_in[3];
    const float* w2a = (const float*)d_in[4];
    const float* b2a = (const float*)d_in[5];
    const float* w3a = (const float*)d_in[6];
    const float* b3a = (const float*)d_in[7];
    const float* w1b = (const float*)d_in[8];
    const float* b1b = (const float*)d_in[9];
    const float* w2b = (const float*)d_in[10];
    const float* b2b = (const float*)d_in[11];
    const float* w3b = (const float*)d_in[12];
    const float* b3b = (const float*)d_in[13];
    const float* lw1 = (const float*)d_in[14];
    const float* lb1 = (const float*)d_in[15];
    const float* lw2 = (const float*)d_in[16];
    const float* lb2 = (const float*)d_in[17];

    float* outf = (float*)d_out;                       // [HW, 2]
    float* den1 = (float*)d_out + (size_t)2 * HWdim;   // [H, W, 6]
    float* den2 = (float*)d_out + (size_t)8 * HWdim;   // [H, W, 6]

    cudaFuncSetAttribute(unet_fused_kernel,
                         cudaFuncAttributeMaxDynamicSharedMemorySize, SMEM_BYTES);

    fold_mlp_kernel<<<1, 32>>>(lw1, lb1, lw2, lb2);

    dim3 grid(Wdim / TSW, Hdim / TSH);
    unet_fused_kernel<<<grid, NT, SMEM_BYTES>>>(
        x, x2, w1a, b1a, w2a, b2a, w3a, b3a,
        w1b, b1b, w2b, b2b, w3b, b3b,
        outf, den1, den2);
}

// round 15
// speedup vs baseline: 1.1028x; 1.1028x over previous
#include <cuda_runtime.h>

#define Hdim 1024
#define Wdim 1024
#define HWdim (Hdim * Wdim)
#define TSH 32
#define TSW 32
#define NT 128

// smem float offsets (all even -> 8B alignment for float2 LDS)
#define OFF_X   0            // [3][38][38]
#define OFF_C4  4332         // [36][36]
#define OFF_C5  5628         // [34][34]
#define OFF_W   6784         // [108]
#define OFF_B   6892         // [3]
#define OFF_M   6896         // [12]
#define OFF_B2  6908         // [2]
#define SMEM_FLOATS 6910
#define SMEM_BYTES (SMEM_FLOATS * 4)

__device__ float g_M[12];
__device__ float g_B[2];

__global__ void fold_mlp_kernel(const float* __restrict__ lw1,
                                const float* __restrict__ lb1,
                                const float* __restrict__ lw2,
                                const float* __restrict__ lb2) {
    int t = threadIdx.x;
    if (t < 12) {
        int o = t / 6, c = t % 6;
        float acc = 0.0f;
        #pragma unroll 8
        for (int k = 0; k < 128; k++)
            acc += lw2[o * 128 + k] * lw1[k * 6 + c];
        g_M[t] = acc;
    } else if (t < 14) {
        int o = t - 12;
        float acc = lb2[o];
        #pragma unroll 8
        for (int k = 0; k < 128; k++)
            acc += lw2[o * 128 + k] * lb1[k];
        g_B[o] = acc;
    }
}

__device__ __forceinline__ float sigmoidf_(float y) {
    return __fdividef(1.0f, 1.0f + __expf(-y));
}

// 2x2-output conv accumulate, window starts at P (P must be 8B-aligned).
// 2 x LDS.64 per row. Accumulates into a00, a01, a10, a11.
#define ACC2X2_EVEN(P, S, WSM) do {                                          \
    float wc[9];                                                             \
    _Pragma("unroll")                                                        \
    for (int kk = 0; kk < 9; kk++) wc[kk] = (WSM)[kk];                       \
    _Pragma("unroll")                                                        \
    for (int rr = 0; rr < 4; rr++) {                                         \
        float2 A = *(const float2*)((P) + rr * (S));                         \
        float2 B = *(const float2*)((P) + rr * (S) + 2);                     \
        if (rr <= 2) {                                                       \
            a00 += wc[rr*3+0]*A.x + wc[rr*3+1]*A.y + wc[rr*3+2]*B.x;         \
            a01 += wc[rr*3+0]*A.y + wc[rr*3+1]*B.x + wc[rr*3+2]*B.y;         \
        }                                                                    \
        if (rr >= 1) {                                                       \
            a10 += wc[(rr-1)*3+0]*A.x + wc[(rr-1)*3+1]*A.y + wc[(rr-1)*3+2]*B.x; \
            a11 += wc[(rr-1)*3+0]*A.y + wc[(rr-1)*3+1]*B.x + wc[(rr-1)*3+2]*B.y; \
        }                                                                    \
    }                                                                        \
} while (0)

// Same, but the logical window starts at P+1 (P 8B-aligned): 3 x LDS.64 per row.
#define ACC2X2_ODD(P, S, WSM) do {                                           \
    float wc[9];                                                             \
    _Pragma("unroll")                                                        \
    for (int kk = 0; kk < 9; kk++) wc[kk] = (WSM)[kk];                       \
    _Pragma("unroll")                                                        \
    for (int rr = 0; rr < 4; rr++) {                                         \
        float2 A = *(const float2*)((P) + rr * (S));                         \
        float2 B = *(const float2*)((P) + rr * (S) + 2);                     \
        float2 C = *(const float2*)((P) + rr * (S) + 4);                     \
        if (rr <= 2) {                                                       \
            a00 += wc[rr*3+0]*A.y + wc[rr*3+1]*B.x + wc[rr*3+2]*B.y;         \
            a01 += wc[rr*3+0]*B.x + wc[rr*3+1]*B.y + wc[rr*3+2]*C.x;         \
        }                                                                    \
        if (rr >= 1) {                                                       \
            a10 += wc[(rr-1)*3+0]*A.y + wc[(rr-1)*3+1]*B.x + wc[(rr-1)*3+2]*B.y; \
            a11 += wc[(rr-1)*3+0]*B.x + wc[(rr-1)*3+1]*B.y + wc[(rr-1)*3+2]*C.x; \
        }                                                                    \
    }                                                                        \
} while (0)

template <bool INTERIOR>
__device__ __forceinline__ void encoder_pass(
    float* __restrict__ sm, int tid, int h0, int w0, int e,
    const float* __restrict__ X,
    const float* __restrict__ W1, const float* __restrict__ W2,
    const float* __restrict__ W3,
    const float* __restrict__ B1, const float* __restrict__ B2c,
    const float* __restrict__ B3,
    float* __restrict__ den, float* __restrict__ outf)
{
    float* s_x  = sm + OFF_X;    // [3][38][38]
    float* s_c4 = sm + OFF_C4;   // [36][36]
    float* s_c5 = sm + OFF_C5;   // [34][34]
    float* s_w  = sm + OFF_W;
    float* s_b  = sm + OFF_B;
    float* s_M  = sm + OFF_M;
    float* s_B2 = sm + OFF_B2;

    // ---- weights + biases ----
    if (tid < 108) {
        float v;
        if (tid < 27)      v = __ldg(&W1[tid]);
        else if (tid < 63) v = __ldg(&W2[tid - 27]);
        else               v = __ldg(&W3[tid - 63]);
        s_w[tid] = v;
    }
    if (tid == 120) s_b[0] = __ldg(&B1[0]);
    if (tid == 121) s_b[1] = __ldg(&B2c[0]);
    if (tid == 122) s_b[2] = __ldg(&B3[0]);

    // ---- input tile (3 ch, 38x38, 3-halo) ----
    #pragma unroll 1
    for (int c = 0; c < 3; c++) {
        const float* Xc = X + c * HWdim + (h0 - 3) * Wdim + (w0 - 3);
        #pragma unroll 1
        for (int idx = tid; idx < 38 * 38; idx += NT) {
            int r = idx / 38;
            int q = idx - r * 38;
            float v;
            if (INTERIOR) {
                v = __ldg(&Xc[r * Wdim + q]);
            } else {
                int gh = h0 - 3 + r, gw = w0 - 3 + q;
                v = 0.0f;
                if ((unsigned)gh < (unsigned)Hdim && (unsigned)gw < (unsigned)Wdim)
                    v = __ldg(&X[c * HWdim + gh * Wdim + gw]);
            }
            s_x[c * 1444 + idx] = v;
        }
    }
    __syncthreads();

    // ===== conv1: 3ch -> c4 (36x36), 2x2 blocked =====
    // Outside-image positions must be 0 (reference zero-pads the
    // concatenated tensor) -- only relevant for border blocks.
    {
        #pragma unroll 1
        for (int item = tid; item < 18 * 18; item += NT) {
            int jp = item / 18;
            int ip = item - jp * 18;
            int j = jp * 2, i = ip * 2;
            float a00 = 0, a01 = 0, a10 = 0, a11 = 0;
            ACC2X2_EVEN(s_x + 0 * 1444 + j * 38 + i, 38, s_w + 0);
            ACC2X2_EVEN(s_x + 1 * 1444 + j * 38 + i, 38, s_w + 9);
            ACC2X2_EVEN(s_x + 2 * 1444 + j * 38 + i, 38, s_w + 18);
            float bia = s_b[0];
            float2 r0, r1;
            if (INTERIOR) {
                r0 = make_float2(sigmoidf_(bia + a00), sigmoidf_(bia + a01));
                r1 = make_float2(sigmoidf_(bia + a10), sigmoidf_(bia + a11));
            } else {
                int gw = w0 + i - 2, gh = h0 + j - 2;
                bool wc0 = (unsigned)gw < (unsigned)Wdim;
                bool wc1 = (unsigned)(gw + 1) < (unsigned)Wdim;
                bool hc0 = (unsigned)gh < (unsigned)Hdim;
                bool hc1 = (unsigned)(gh + 1) < (unsigned)Hdim;
                r0 = make_float2(hc0 && wc0 ? sigmoidf_(bia + a00) : 0.0f,
                                 hc0 && wc1 ? sigmoidf_(bia + a01) : 0.0f);
                r1 = make_float2(hc1 && wc0 ? sigmoidf_(bia + a10) : 0.0f,
                                 hc1 && wc1 ? sigmoidf_(bia + a11) : 0.0f);
            }
            *(float2*)(s_c4 + j * 36 + i)       = r0;
            *(float2*)(s_c4 + (j + 1) * 36 + i) = r1;
        }
    }
    __syncthreads();

    // ===== conv2: [x,c4] -> c5 (34x34), 2x2 blocked =====
    {
        #pragma unroll 1
        for (int item = tid; item < 17 * 17; item += NT) {
            int jp = item / 17;
            int ip = item - jp * 17;
            int j = jp * 2, i = ip * 2;
            float a00 = 0, a01 = 0, a10 = 0, a11 = 0;
            ACC2X2_ODD (s_x + 0 * 1444 + (j + 1) * 38 + i, 38, s_w + 27);
            ACC2X2_ODD (s_x + 1 * 1444 + (j + 1) * 38 + i, 38, s_w + 36);
            ACC2X2_ODD (s_x + 2 * 1444 + (j + 1) * 38 + i, 38, s_w + 45);
            ACC2X2_EVEN(s_c4 + j * 36 + i,                  36, s_w + 54);
            float bia = s_b[1];
            float2 r0, r1;
            if (INTERIOR) {
                r0 = make_float2(sigmoidf_(bia + a00), sigmoidf_(bia + a01));
                r1 = make_float2(sigmoidf_(bia + a10), sigmoidf_(bia + a11));
            } else {
                int gw = w0 + i - 1, gh = h0 + j - 1;
                bool wc0 = (unsigned)gw < (unsigned)Wdim;
                bool wc1 = (unsigned)(gw + 1) < (unsigned)Wdim;
                bool hc0 = (unsigned)gh < (unsigned)Hdim;
                bool hc1 = (unsigned)(gh + 1) < (unsigned)Hdim;
                r0 = make_float2(hc0 && wc0 ? sigmoidf_(bia + a00) : 0.0f,
                                 hc0 && wc1 ? sigmoidf_(bia + a01) : 0.0f);
                r1 = make_float2(hc1 && wc0 ? sigmoidf_(bia + a10) : 0.0f,
                                 hc1 && wc1 ? sigmoidf_(bia + a11) : 0.0f);
            }
            *(float2*)(s_c5 + j * 34 + i)       = r0;
            *(float2*)(s_c5 + (j + 1) * 34 + i) = r1;
        }
    }
    __syncthreads();

    // ===== conv3: [x,c4,c5] -> c6 + den + outf (32x32), 2 quads/thread =====
    {
        #pragma unroll 1
        for (int k = 0; k < 2; k++) {
            int item = tid + k * NT;   // 256 items exactly (16x16 quads)
            int jp = item >> 4;
            int ip = item & 15;
            int j = jp * 2, i = ip * 2;
            float a00 = 0, a01 = 0, a10 = 0, a11 = 0;
            ACC2X2_EVEN(s_x + 0 * 1444 + (j + 2) * 38 + (i + 2), 38, s_w + 63);
            ACC2X2_EVEN(s_x + 1 * 1444 + (j + 2) * 38 + (i + 2), 38, s_w + 72);
            ACC2X2_EVEN(s_x + 2 * 1444 + (j + 2) * 38 + (i + 2), 38, s_w + 81);
            ACC2X2_ODD (s_c4 + (j + 1) * 36 + i,                  36, s_w + 90);
            ACC2X2_EVEN(s_c5 + j * 34 + i,                        34, s_w + 99);
            float bia = s_b[2];

            float accs[2][2] = {{a00, a01}, {a10, a11}};
            #pragma unroll
            for (int r = 0; r < 2; r++) {
                int jj = j + r;
                float fA5 = sigmoidf_(bia + accs[r][0]);
                float fB5 = sigmoidf_(bia + accs[r][1]);
                const float* xc = s_x + (jj + 3) * 38 + (i + 3);
                float fA0 = xc[0],    fB0 = xc[1];
                float fA1 = xc[1444], fB1 = xc[1445];
                float fA2 = xc[2888], fB2 = xc[2889];
                float fA3 = s_c4[(jj + 2) * 36 + (i + 2)];
                float fB3 = s_c4[(jj + 2) * 36 + (i + 3)];
                float fA4 = s_c5[(jj + 1) * 34 + (i + 1)];
                float fB4 = s_c5[(jj + 1) * 34 + (i + 2)];

                int pix = (h0 + jj) * Wdim + (w0 + i);   // even
                float4* dp = (float4*)(den + (size_t)pix * 6);
                dp[0] = make_float4(fA0, fA1, fA2, fA3);
                dp[1] = make_float4(fA4, fA5, fB0, fB1);
                dp[2] = make_float4(fB2, fB3, fB4, fB5);

                float mA0 = s_M[0]*fA0 + s_M[1]*fA1 + s_M[2]*fA2
                          + s_M[3]*fA3 + s_M[4]*fA4 + s_M[5]*fA5;
                float mA1 = s_M[6]*fA0 + s_M[7]*fA1 + s_M[8]*fA2
                          + s_M[9]*fA3 + s_M[10]*fA4 + s_M[11]*fA5;
                float mB0 = s_M[0]*fB0 + s_M[1]*fB1 + s_M[2]*fB2
                          + s_M[3]*fB3 + s_M[4]*fB4 + s_M[5]*fB5;
                float mB1 = s_M[6]*fB0 + s_M[7]*fB1 + s_M[8]*fB2
                          + s_M[9]*fB3 + s_M[10]*fB4 + s_M[11]*fB5;

                float4* op = (float4*)(outf + (size_t)pix * 2);
                if (e == 0) {
                    *op = make_float4(s_B2[0] + mA0, s_B2[1] + mA1,
                                      s_B2[0] + mB0, s_B2[1] + mB1);
                } else {
                    float4 prev = *op;  // same thread wrote it in e=0
                    *op = make_float4(prev.x - mA0, prev.y - mA1,
                                      prev.z - mB0, prev.w - mB1);
                }
            }
        }
    }
}

__global__ __launch_bounds__(NT, 8) void unet_fused_kernel(
    const float* __restrict__ x,  const float* __restrict__ x2,
    const float* __restrict__ w1a, const float* __restrict__ b1a,
    const float* __restrict__ w2a, const float* __restrict__ b2a,
    const float* __restrict__ w3a, const float* __restrict__ b3a,
    const float* __restrict__ w1b, const float* __restrict__ b1b,
    const float* __restrict__ w2b, const float* __restrict__ b2b,
    const float* __restrict__ w3b, const float* __restrict__ b3b,
    float* __restrict__ outf, float* __restrict__ den1, float* __restrict__ den2)
{
    extern __shared__ float sm[];
    const int tid = threadIdx.x;
    const int h0  = blockIdx.y * TSH;
    const int w0  = blockIdx.x * TSW;

    if (tid < 12) (sm + OFF_M)[tid] = g_M[tid];
    if (tid >= 12 && tid < 14) (sm + OFF_B2)[tid - 12] = g_B[tid - 12];

    const bool interior = (h0 >= 3) && (h0 + TSH + 3 <= Hdim)
                       && (w0 >= 3) && (w0 + TSW + 3 <= Wdim);

    if (interior) {
        #pragma unroll 1
        for (int e = 0; e < 2; e++) {
            __syncthreads();
            encoder_pass<true>(sm, tid, h0, w0, e,
                e ? x2 : x,
                e ? w1b : w1a, e ? w2b : w2a, e ? w3b : w3a,
                e ? b1b : b1a, e ? b2b : b2a, e ? b3b : b3a,
                e ? den2 : den1, outf);
        }
    } else {
        #pragma unroll 1
        for (int e = 0; e < 2; e++) {
            __syncthreads();
            encoder_pass<false>(sm, tid, h0, w0, e,
                e ? x2 : x,
                e ? w1b : w1a, e ? w2b : w2a, e ? w3b : w3a,
                e ? b1b : b1a, e ? b2b : b2a, e ? b3b : b3a,
                e ? den2 : den1, outf);
        }
    }
}

extern "C" void kernel_launch(void* const* d_in, const int* in_sizes, int n_in,
                              void* d_out, int out_size) {
    const float* x   = (const float*)d_in[0];
    const float* x2  = (const float*)d_in[1];
    const float* w1a = (const float*)d_in[2];
    const float* b1a = (const float*)d_in[3];
    const float* w2a = (const float*)d_in[4];
    const float* b2a = (const float*)d_in[5];
    const float* w3a = (const float*)d_in[6];
    const float* b3a = (const float*)d_in[7];
    const float* w1b = (const float*)d_in[8];
    const float* b1b = (const float*)d_in[9];
    const float* w2b = (const float*)d_in[10];
    const float* b2b = (const float*)d_in[11];
    const float* w3b = (const float*)d_in[12];
    const float* b3b = (const float*)d_in[13];
    const float* lw1 = (const float*)d_in[14];
    const float* lb1 = (const float*)d_in[15];
    const float* lw2 = (const float*)d_in[16];
    const float* lb2 = (const float*)d_in[17];

    float* outf = (float*)d_out;                       // [HW, 2]
    float* den1 = (float*)d_out + (size_t)2 * HWdim;   // [H, W, 6]
    float* den2 = (float*)d_out + (size_t)8 * HWdim;   // [H, W, 6]

    cudaFuncSetAttribute(unet_fused_kernel,
                         cudaFuncAttributeMaxDynamicSharedMemorySize, SMEM_BYTES);

    fold_mlp_kernel<<<1, 32>>>(lw1, lb1, lw2, lb2);

    dim3 grid(Wdim / TSW, Hdim / TSH);
    unet_fused_kernel<<<grid, NT, SMEM_BYTES>>>(
        x, x2, w1a, b1a, w2a, b2a, w3a, b3a,
        w1b, b1b, w2b, b2b, w3b, b3b,
        outf, den1, den2);
}